// round 8
// baseline (speedup 1.0000x reference)
#include <cuda_runtime.h>

// Trilinear resize [4,128,128,128,2] f32 -> [4,192,192,192,2] f32, zoom=1.5.
// Exact 3-out-per-2-in periodicity, weights {1, 1/3, 2/3}.
// Phase 1: cooperative load + X-LERP into smem (x-resampled rows, float4-paired).
//   task (r, j): 5 input voxels -> 3 float4 outputs (6 output x columns).
// Phase 2: thread = (x-pair, yg, zg); 9 conflict-free LDS.128, y/z lerps on
//   float4, 9 perfectly coalesced STG.128.
// Block = (b, zkp, ykp): output 192 x 6 x 6 from input 128 x 5 x 5.

#define IN_D  128
#define OUT_D 192

__device__ __forceinline__ float4 lerp4(float4 a, float4 b, float wa, float wb) {
    return make_float4(fmaf(a.x, wa, b.x * wb), fmaf(a.y, wa, b.y * wb),
                       fmaf(a.z, wa, b.z * wb), fmaf(a.w, wa, b.w * wb));
}

__global__ __launch_bounds__(384) void resize_xlerp_smem_kernel(
    const float2* __restrict__ in,   // [4,128,128,128] voxels (C=2 packed)
    float4* __restrict__ out)        // [4,192,192,96] float4 (x-pairs)
{
    __shared__ float4 xtile[25][96];   // [zi*5+yj][x-pair], 38400 B

    const int blk = blockIdx.x;
    const int ykp = blk & 31;          // output y / 6
    const int zkp = (blk >> 5) & 31;   // output z / 6
    const int b   = blk >> 10;

    const int t = threadIdx.x;         // 0..383

    const float c13 = 1.0f / 3.0f;
    const float c23 = 2.0f / 3.0f;

    const float2* base = in + (size_t)b * (IN_D * IN_D * IN_D);

    // ---- Phase 1: load + x-lerp 25 rows x 32 chunks = 800 tasks ----
    #pragma unroll
    for (int i = 0; i < 3; i++) {
        int tau = i * 384 + t;
        if (tau < 800) {
            int r = tau >> 5;          // 0..24
            int j = tau & 31;          // chunk: input x 4j..4j+4 -> out x 6j..6j+5
            int zi = r / 5;
            int yj = r - 5 * zi;
            int z = min(4 * zkp + zi, IN_D - 1);
            int y = min(4 * ykp + yj, IN_D - 1);
            const float2* row = base + ((size_t)z * IN_D + y) * IN_D;
            float4 A = __ldg((const float4*)(row + 4 * j));       // a0,a1
            float4 B = __ldg((const float4*)(row + 4 * j + 2));   // a2,a3
            float2 a4 = __ldg(row + min(4 * j + 4, IN_D - 1));

            xtile[r][3 * j + 0] = make_float4(
                A.x, A.y,
                fmaf(A.x, c13, A.z * c23), fmaf(A.y, c13, A.w * c23));
            xtile[r][3 * j + 1] = make_float4(
                fmaf(A.z, c23, B.x * c13), fmaf(A.w, c23, B.y * c13),
                B.x, B.y);
            xtile[r][3 * j + 2] = make_float4(
                fmaf(B.x, c13, B.z * c23), fmaf(B.y, c13, B.w * c23),
                fmaf(B.z, c23, a4.x * c13), fmaf(B.w, c23, a4.y * c13));
        }
    }
    __syncthreads();

    // ---- Phase 2: y/z lerp + wide stores ----
    const int p  = t % 96;             // output x-pair
    const int g  = t / 96;             // 0..3
    const int yg = g & 1;              // y micro-block within pair
    const int zg = g >> 1;             // z micro-block within pair

    const int rbase = 2 * zg * 5 + 2 * yg;   // row of (zi=0, yi=0)

    // y-lerp of input plane zi (3 smem rows -> 3 output-y float4)
    auto plane = [&](int zi, float4 u[3]) {
        const int r = rbase + 5 * zi;
        float4 q0 = xtile[r + 0][p];
        float4 q1 = xtile[r + 1][p];
        float4 q2 = xtile[r + 2][p];
        u[0] = q0;
        u[1] = lerp4(q0, q1, c13, c23);
        u[2] = lerp4(q1, q2, c23, c13);
    };

    float4 u0[3], u1[3], u2[3];
    plane(0, u0);
    plane(1, u1);
    plane(2, u2);

    size_t ob = (((size_t)b * OUT_D + (6 * zkp + 3 * zg)) * OUT_D
                 + (6 * ykp + 3 * yg)) * 96 + p;

    #pragma unroll
    for (int yo = 0; yo < 3; yo++) {
        out[ob + (size_t)(0 * OUT_D + yo) * 96] = u0[yo];
        out[ob + (size_t)(1 * OUT_D + yo) * 96] = lerp4(u0[yo], u1[yo], c13, c23);
        out[ob + (size_t)(2 * OUT_D + yo) * 96] = lerp4(u1[yo], u2[yo], c23, c13);
    }
}

extern "C" void kernel_launch(void* const* d_in, const int* in_sizes, int n_in,
                              void* d_out, int out_size) {
    const float2* in = (const float2*)d_in[0];
    float4* out = (float4*)d_out;

    int blocks = 4 * 32 * 32;   // (b, zkp, ykp) = 4096
    resize_xlerp_smem_kernel<<<blocks, 384>>>(in, out);
}

// round 9
// speedup vs baseline: 1.0287x; 1.0287x over previous
#include <cuda_runtime.h>

// Trilinear resize [4,128,128,128,2] f32 -> [4,192,192,192,2] f32, zoom=1.5.
// Exact 3-out-per-2-in periodicity, weights {1, 1/3, 2/3}.
// Best-known skeleton (R3): block = (b, zk, yk), input strip [3z][3y][128x]
// staged in smem via float4 cooperative loads; thread = output x column,
// y/z lerps in registers, 27 perfectly coalesced STG with streaming (.cs)
// hint (output is write-once, never re-read).

#define IN_D  128
#define OUT_D 192

__device__ __forceinline__ float2 lerp2(float2 a, float2 b, float wa, float wb) {
    return make_float2(fmaf(a.x, wa, b.x * wb), fmaf(a.y, wa, b.y * wb));
}

__global__ __launch_bounds__(192) void resize_smem_cs_kernel(
    const float2* __restrict__ in,   // [4,128,128,128] voxels (C=2 packed)
    float2* __restrict__ out)        // [4,192,192,192] voxels
{
    __shared__ float2 tile[9][IN_D];   // [zi*3+yi][x], 9216 B

    const int blk = blockIdx.x;
    const int yk = blk & 63;
    const int zk = (blk >> 6) & 63;
    const int b  = blk >> 12;

    const int t = threadIdx.x;         // 0..191

    const float4* in4 = (const float4*)(in + (size_t)b * (IN_D * IN_D * IN_D));
    float4* tile4 = (float4*)tile;

    // ---- Phase 1: cooperative float4 load of 9 input rows (576 float4) ----
    #pragma unroll
    for (int i = 0; i < 3; i++) {
        int idx = i * 192 + t;         // 0..575
        int f4 = idx & 63;             // float4 index within row
        int r  = idx >> 6;             // 0..8
        int zi = r / 3;
        int yi = r - 3 * zi;
        int z = min(2 * zk + zi, IN_D - 1);
        int y = min(2 * yk + yi, IN_D - 1);
        tile4[idx] = __ldg(in4 + ((size_t)z * IN_D + y) * 64 + f4);
    }
    __syncthreads();

    const float c13 = 1.0f / 3.0f;
    const float c23 = 2.0f / 3.0f;

    // x-taps and weights for this output column (m = t % 3)
    const int q = t / 3;
    const int m = t - 3 * q;
    int xA, xB;
    float wA;
    if (m == 0)      { xA = 2 * q;     xB = xA;                       wA = 1.0f; }
    else if (m == 1) { xA = 2 * q;     xB = 2 * q + 1;                wA = c13;  }
    else             { xA = 2 * q + 1; xB = min(2 * q + 2, IN_D - 1); wA = c23;  }
    const float wB = 1.0f - wA;

    // x-lerp from smem + y-lerp, per input z plane
    float2 yl[3][3];                   // [zi][yo]
    #pragma unroll
    for (int zi = 0; zi < 3; zi++) {
        float2 xv[3];
        #pragma unroll
        for (int yi = 0; yi < 3; yi++) {
            float2 a = tile[zi * 3 + yi][xA];
            float2 c = tile[zi * 3 + yi][xB];
            xv[yi] = lerp2(a, c, wA, wB);
        }
        yl[zi][0] = xv[0];
        yl[zi][1] = lerp2(xv[0], xv[1], c13, c23);
        yl[zi][2] = lerp2(xv[1], xv[2], c23, c13);
    }

    // z-lerp + 27 coalesced streaming stores
    float2* obase = out +
        ((((size_t)b * OUT_D + 3 * zk) * OUT_D + 3 * yk) * OUT_D + t);
    #pragma unroll
    for (int yo = 0; yo < 3; yo++) {
        float2 v0 = yl[0][yo];
        float2 v1 = yl[1][yo];
        float2 v2 = yl[2][yo];
        __stcs(obase + (size_t)(0 * OUT_D + yo) * OUT_D, v0);
        __stcs(obase + (size_t)(1 * OUT_D + yo) * OUT_D, lerp2(v0, v1, c13, c23));
        __stcs(obase + (size_t)(2 * OUT_D + yo) * OUT_D, lerp2(v1, v2, c23, c13));
    }
}

extern "C" void kernel_launch(void* const* d_in, const int* in_sizes, int n_in,
                              void* d_out, int out_size) {
    const float2* in = (const float2*)d_in[0];
    float2* out = (float2*)d_out;

    int blocks = 4 * 64 * 64;   // (b, zk, yk) = 16384
    resize_smem_cs_kernel<<<blocks, 192>>>(in, out);
}